// round 16
// baseline (speedup 1.0000x reference)
#include <cuda_runtime.h>
#include <cuda_bf16.h>

// torchSOM: sequential SOM training, 2000 iterations, single persistent CTA.
// nodes [1024,32] live NEGATED in registers (1 thread = 1 node row).
// Bit-exact XLA-GPU rounding: per-lane square (mul.rn) + shfl-down-tree
// association (16,8,4,2,1) + sqrt.rn; un-fused mul/add update; exact schedule.
// R13: restructured to fit 64 regs/thread (1024 thr) with NO spills:
//  - reduction tree fused into the diff loop (4 accumulators, same association)
//  - update recomputes diff (nn unchanged since dist -> bit-identical)
//  - alpha (fdiv) computed once in warp 0, broadcast via smem on bar2

#define DDIM 32
#define NITER_C 2000

typedef unsigned long long u64;
typedef unsigned int u32;

__device__ __forceinline__ u64 pack2(float lo, float hi) {
    u64 r;
    asm("mov.b64 %0, {%1, %2};" : "=l"(r) : "f"(lo), "f"(hi));
    return r;
}
__device__ __forceinline__ void unpack2(u64 v, float& lo, float& hi) {
    asm("mov.b64 {%0, %1}, %2;" : "=f"(lo), "=f"(hi) : "l"(v));
}
// Packed IEEE-rn f32x2 ops (per-lane semantics identical to scalar rn ops).
#define ADD2(out, a, b) \
    asm("add.rn.f32x2 %0, %1, %2;" : "=l"(out) : "l"(a), "l"(b))
#define MUL2(out, a, b) \
    asm("mul.rn.f32x2 %0, %1, %2;" : "=l"(out) : "l"(a), "l"(b))

__global__ __launch_bounds__(1024, 1)
void som_train_kernel(const float* __restrict__ data,
                      const float* __restrict__ nodes,
                      const int* __restrict__ rand_indices,
                      float* __restrict__ out)
{
    // x row triple buffer: the write at iter k+1 start is separated from the
    // last conflicting read (iter k-1's update loop) by iter k's barriers.
    __shared__ __align__(16) float xs[3][DDIM];
    __shared__ u32 wbits[32];
    __shared__ u32 widx[32];
    __shared__ int winner;
    __shared__ float neg_alpha_sh;

    const int tid  = threadIdx.x;
    const int lane = tid & 31;
    const int wid  = tid >> 5;
    const int mr   = tid >> 5;   // lattice row of this node
    const int mc   = tid & 31;   // lattice col of this node

    // Load this thread's node row, negated (negation is exact), packed.
    u64 nn[16];
#pragma unroll
    for (int j = 0; j < 16; j++) {
        float a = nodes[tid * DDIM + 2 * j];
        float b = nodes[tid * DDIM + 2 * j + 1];
        nn[j] = pack2(-a, -b);
    }

    // Preload x for iteration 0.
    if (tid < DDIM) {
        int i0 = rand_indices[0];
        xs[0][tid] = data[(size_t)i0 * DDIM + tid];
    }
    __syncthreads();

    float th = 20.0f;  // THRESH0

    for (int k = 0; k < NITER_C; k++) {
        const u64* __restrict__ x2 = (const u64*)xs[k % 3];

        // Prefetch next iteration's x row (warp 31, overlapped with compute).
        if (tid >= 992 && (k + 1) < NITER_C) {
            int ni = rand_indices[k + 1];
            xs[(k + 1) % 3][tid - 992] = data[(size_t)ni * DDIM + (tid - 992)];
        }

        // ---- dist^2 with XLA shfl.down(16,8,4,2,1) tree association ----
        // Packed reg j holds dims (2j, 2j+1); lane pairs (d, d+16) -> regs
        // (j, j+8). Fused form with 4 accumulators, association preserved:
        //   s4[j] = (m[j] + m[j+8]) + (m[j+4] + m[j+12])
        u64 s[4];
#pragma unroll
        for (int j = 0; j < 4; j++) {
            u64 t0, t1, t2, t3;
            ADD2(t0, x2[j],      nn[j]);      MUL2(t0, t0, t0);
            ADD2(t1, x2[j + 8],  nn[j + 8]);  MUL2(t1, t1, t1);
            ADD2(t2, x2[j + 4],  nn[j + 4]);  MUL2(t2, t2, t2);
            ADD2(t3, x2[j + 12], nn[j + 12]); MUL2(t3, t3, t3);
            ADD2(t0, t0, t1);   // m[j]   + m[j+8]   (offset-16 stage)
            ADD2(t2, t2, t3);   // m[j+4] + m[j+12]
            ADD2(s[j], t0, t2); // offset-8 stage
        }
        ADD2(s[0], s[0], s[2]); // offset-4 stage
        ADD2(s[1], s[1], s[3]);
        ADD2(s[0], s[0], s[1]); // offset-2 stage
        float lo, hi;
        unpack2(s[0], lo, hi);
        float ss   = __fadd_rn(lo, hi);  // offset-1 stage
        float dist = __fsqrt_rn(ss);

        // ---- block argmin on dist, ties -> lowest node index ----
        // dist >= 0, so float bits are order-isomorphic to u32.
        u32 bits = __float_as_uint(dist);
        u32 wmin = __reduce_min_sync(0xffffffffu, bits);
        u32 ball = __ballot_sync(0xffffffffu, bits == wmin);
        if (lane == 0) {
            wbits[wid] = wmin;
            widx[wid]  = (u32)((wid << 5) + (__ffs(ball) - 1));
        }
        __syncthreads();  // bar1
        if (wid == 0) {
            u32 b  = wbits[lane];
            u32 m2 = __reduce_min_sync(0xffffffffu, b);
            u32 bl = __ballot_sync(0xffffffffu, b == m2);
            if (lane == 0) winner = (int)widx[__ffs(bl) - 1];
            if (lane == 1) {
                // alpha schedule, exact rn chain, computed once per iter
                float kf = (float)k;
                float a  = __fsub_rn(0.05f,
                             __fmul_rn(0.04f, __fdiv_rn(kf, 2000.0f)));
                neg_alpha_sh = -a;
            }
        }
        __syncthreads();  // bar2
        const int   nearest = winner;
        const float nalpha  = neg_alpha_sh;

        // ---- deterministic threshold schedule ----
        th = fmaxf(th, 0.5f);

        // ---- masked neighborhood update: Chebyshev lattice distance ----
        int dr   = mr - (nearest >> 5); if (dr < 0) dr = -dr;
        int dc   = mc - (nearest & 31); if (dc < 0) dc = -dc;
        int cheb = dr > dc ? dr : dc;
        if ((float)cheb <= th) {
            // reference: n' = rn(n + rn(diff*alpha)); negated storage:
            // nn' = rn(nn + rn(diff*(-alpha))) — bit-identical under negation.
            // diff recomputed: nn unchanged since dist -> identical bits.
            u64 na = pack2(nalpha, nalpha);
#pragma unroll
            for (int j = 0; j < 16; j++) {
                u64 t;
                ADD2(t, x2[j], nn[j]);   // diff = x - node
                MUL2(t, t, na);          // rn(diff * -alpha)
                ADD2(nn[j], nn[j], t);   // rn(nn + t)
            }
        }
        th = __fadd_rn(th, -0.00975f);  // THRESH_STEP
    }

    // ---- write final nodes (un-negate, exact) ----
#pragma unroll
    for (int j = 0; j < 16; j++) {
        float a, b;
        unpack2(nn[j], a, b);
        out[tid * DDIM + 2 * j]     = -a;
        out[tid * DDIM + 2 * j + 1] = -b;
    }
}

extern "C" void kernel_launch(void* const* d_in, const int* in_sizes, int n_in,
                              void* d_out, int out_size) {
    // Robust input binding by element count:
    // data 500000*32, nodes 1024*32, nhbrdist 1024*1024 (unused), rand 2000.
    const float* data   = nullptr;
    const float* nodes  = nullptr;
    const int*   ridx   = nullptr;
    for (int i = 0; i < n_in; i++) {
        if      (in_sizes[i] == 500000 * 32) data  = (const float*)d_in[i];
        else if (in_sizes[i] == 1024 * 32)   nodes = (const float*)d_in[i];
        else if (in_sizes[i] == 2000)        ridx  = (const int*)d_in[i];
    }
    som_train_kernel<<<1, 1024>>>(data, nodes, ridx, (float*)d_out);
}

// round 17
// speedup vs baseline: 1.1455x; 1.1455x over previous
#include <cuda_runtime.h>
#include <cuda_bf16.h>

// torchSOM: sequential SOM training, 2000 iterations, single persistent CTA.
// nodes [1024,32] live NEGATED in registers (1 thread = 1 node row).
// Bit-exact XLA-GPU rounding: per-lane square (mul.rn) + shfl-down-tree
// association (16,8,4,2,1) + sqrt.rn; un-fused mul/add update; exact schedule.
// R16: single-barrier argmin (redundant per-warp final stage, double-buffered
// partials), LDS.128 x loads, alpha/threshold/rand tables precomputed in smem.

#define DDIM 32
#define NITER_C 2000

typedef unsigned long long u64;
typedef unsigned int u32;

__device__ __forceinline__ u64 pack2(float lo, float hi) {
    u64 r;
    asm("mov.b64 %0, {%1, %2};" : "=l"(r) : "f"(lo), "f"(hi));
    return r;
}
__device__ __forceinline__ void unpack2(u64 v, float& lo, float& hi) {
    asm("mov.b64 {%0, %1}, %2;" : "=f"(lo), "=f"(hi) : "l"(v));
}
// Packed IEEE-rn f32x2 ops (per-lane semantics identical to scalar rn ops).
#define ADD2(out, a, b) \
    asm("add.rn.f32x2 %0, %1, %2;" : "=l"(out) : "l"(a), "l"(b))
#define MUL2(out, a, b) \
    asm("mul.rn.f32x2 %0, %1, %2;" : "=l"(out) : "l"(a), "l"(b))
// 128-bit shared load into two u64 (LDS.128).
#define LDS128_U64(a, b, addr) \
    asm volatile("ld.shared.v2.b64 {%0, %1}, [%2];" \
                 : "=l"(a), "=l"(b) : "r"(addr))

__global__ __launch_bounds__(1024, 1)
void som_train_kernel(const float* __restrict__ data,
                      const float* __restrict__ nodes,
                      const int* __restrict__ rand_indices,
                      float* __restrict__ out)
{
    // x row triple buffer (one barrier/iter still separates conflicting
    // write/read pairs — see race analysis in comments below).
    __shared__ __align__(16) float xs[3][DDIM];
    __shared__ u32 wbits[2][32];       // double-buffered by k&1
    __shared__ u32 widx[2][32];
    __shared__ float nalpha_sh[NITER_C];
    __shared__ signed char lim_sh[NITER_C];
    __shared__ int ridx_sh[NITER_C];

    const int tid  = threadIdx.x;
    const int lane = tid & 31;
    const int wid  = tid >> 5;
    const int mr   = tid >> 5;   // lattice row of this node
    const int mc   = tid & 31;   // lattice col of this node

    // ---- init: schedule tables (exact rn chains) + rand index staging ----
    for (int k = tid; k < NITER_C; k += 1024) {
        float kf = (float)k;                                     // exact
        float a  = __fsub_rn(0.05f,
                     __fmul_rn(0.04f, __fdiv_rn(kf, 2000.0f)));
        nalpha_sh[k] = -a;                                       // exact neg
        ridx_sh[k]   = rand_indices[k];
    }
    if (tid == 0) {
        // serial threshold chain, bit-exact vs reference; store floor(th):
        // for integer cheb>=0 and th>0: (float)cheb <= th  <=>  cheb <= floor(th)
        float th = 20.0f;
        for (int k = 0; k < NITER_C; k++) {
            th = fmaxf(th, 0.5f);
            lim_sh[k] = (signed char)(int)th;
            th = __fadd_rn(th, -0.00975f);
        }
    }

    // Load this thread's node row, negated (negation is exact), packed.
    u64 nn[16];
#pragma unroll
    for (int j = 0; j < 16; j++) {
        float a = nodes[tid * DDIM + 2 * j];
        float b = nodes[tid * DDIM + 2 * j + 1];
        nn[j] = pack2(-a, -b);
    }

    __syncthreads();  // tables ready

    // Preload x for iteration 0 (8 threads of warp 31, 16B vectors).
    if (tid >= 992 && tid < 1000) {
        const uint4* src = (const uint4*)(data + (size_t)ridx_sh[0] * DDIM);
        ((uint4*)xs[0])[tid - 992] = src[tid - 992];
    }
    __syncthreads();

    const u32 xs_base = (u32)__cvta_generic_to_shared(&xs[0][0]);

    for (int k = 0; k < NITER_C; k++) {
        const u32 xa = xs_base + (u32)(k % 3) * (DDIM * 4);
        const int kb = k & 1;

        // Prefetch next iteration's x row (warp 31, overlapped with compute).
        // Writes buf (k+1)%3; last conflicting reads were iter k-2, separated
        // by the iter-(k-1) barrier.
        if (tid >= 992 && tid < 1000 && (k + 1) < NITER_C) {
            const uint4* src =
                (const uint4*)(data + (size_t)ridx_sh[k + 1] * DDIM);
            ((uint4*)xs[(k + 1) % 3])[tid - 992] = src[tid - 992];
        }

        // ---- dist^2 with XLA shfl.down(16,8,4,2,1) tree association ----
        // Packed reg p holds dims (2p,2p+1). Exact association preserved:
        //   s[j] = (m[j] + m[j+8]) + (m[j+4] + m[j+12]),  j = 0..3
        u64 s0, s1, s2, s3;
#pragma unroll
        for (int g = 0; g < 2; g++) {   // g covers j = 2g, 2g+1
            u64 a0, a1, b0, b1, c0, c1, e0, e1, d;
            LDS128_U64(a0, a1, xa + g * 16);        // regs 2g,   2g+1
            LDS128_U64(b0, b1, xa + 64 + g * 16);   // regs 2g+8, 2g+9
            LDS128_U64(c0, c1, xa + 32 + g * 16);   // regs 2g+4, 2g+5
            LDS128_U64(e0, e1, xa + 96 + g * 16);   // regs 2g+12,2g+13
            ADD2(d, a0, nn[2 * g]);      MUL2(a0, d, d);
            ADD2(d, a1, nn[2 * g + 1]);  MUL2(a1, d, d);
            ADD2(d, b0, nn[2 * g + 8]);  MUL2(b0, d, d);
            ADD2(d, b1, nn[2 * g + 9]);  MUL2(b1, d, d);
            ADD2(d, c0, nn[2 * g + 4]);  MUL2(c0, d, d);
            ADD2(d, c1, nn[2 * g + 5]);  MUL2(c1, d, d);
            ADD2(d, e0, nn[2 * g + 12]); MUL2(e0, d, d);
            ADD2(d, e1, nn[2 * g + 13]); MUL2(e1, d, d);
            ADD2(a0, a0, b0);            // m[j]   + m[j+8]   (offset-16)
            ADD2(c0, c0, e0);            // m[j+4] + m[j+12]
            ADD2(a1, a1, b1);
            ADD2(c1, c1, e1);
            u64 se, so;
            ADD2(se, a0, c0);            // offset-8 stage -> s[2g]
            ADD2(so, a1, c1);            //                -> s[2g+1]
            if (g == 0) { s0 = se; s1 = so; } else { s2 = se; s3 = so; }
        }
        ADD2(s0, s0, s2);                // offset-4 stage
        ADD2(s1, s1, s3);
        ADD2(s0, s0, s1);                // offset-2 stage
        float lo, hi;
        unpack2(s0, lo, hi);
        float ss   = __fadd_rn(lo, hi);  // offset-1 stage
        float dist = __fsqrt_rn(ss);

        // ---- block argmin on dist, ties -> lowest node index ----
        // dist >= 0, so float bits are order-isomorphic to u32.
        u32 bits = __float_as_uint(dist);
        u32 wmin = __reduce_min_sync(0xffffffffu, bits);
        u32 ball = __ballot_sync(0xffffffffu, bits == wmin);
        if (lane == 0) {
            wbits[kb][wid] = wmin;
            widx[kb][wid]  = (u32)((wid << 5) + (__ffs(ball) - 1));
        }
        __syncthreads();  // the ONLY barrier per iteration

        // Redundant final stage in every warp (identical results; no bar2).
        {
            u32 b  = wbits[kb][lane];
            u32 iv = widx[kb][lane];
            u32 m2 = __reduce_min_sync(0xffffffffu, b);
            u32 bl = __ballot_sync(0xffffffffu, b == m2);
            int wl = __ffs(bl) - 1;                 // winning warp id
            u32 wi = __shfl_sync(0xffffffffu, iv, wl);
            int nearest = (int)wi;

            // ---- masked neighborhood update: Chebyshev lattice distance ----
            int dr   = mr - (nearest >> 5); if (dr < 0) dr = -dr;
            int dc   = mc - (nearest & 31); if (dc < 0) dc = -dc;
            int cheb = dr > dc ? dr : dc;
            if (cheb <= (int)lim_sh[k]) {
                // reference: n' = rn(n + rn(diff*alpha)); negated storage is
                // bit-identical under exact negation.
                float na = nalpha_sh[k];
                u64 na2 = pack2(na, na);
#pragma unroll
                for (int i = 0; i < 8; i++) {
                    u64 a, b2, t;
                    LDS128_U64(a, b2, xa + i * 16);
                    ADD2(t, a, nn[2 * i]);       // diff (bit-identical redo)
                    MUL2(t, t, na2);             // rn(diff * -alpha)
                    ADD2(nn[2 * i], nn[2 * i], t);
                    ADD2(t, b2, nn[2 * i + 1]);
                    MUL2(t, t, na2);
                    ADD2(nn[2 * i + 1], nn[2 * i + 1], t);
                }
            }
        }
    }

    // ---- write final nodes (un-negate, exact) ----
#pragma unroll
    for (int j = 0; j < 16; j++) {
        float a, b;
        unpack2(nn[j], a, b);
        out[tid * DDIM + 2 * j]     = -a;
        out[tid * DDIM + 2 * j + 1] = -b;
    }
}

extern "C" void kernel_launch(void* const* d_in, const int* in_sizes, int n_in,
                              void* d_out, int out_size) {
    // Robust input binding by element count:
    // data 500000*32, nodes 1024*32, nhbrdist 1024*1024 (unused), rand 2000.
    const float* data   = nullptr;
    const float* nodes  = nullptr;
    const int*   ridx   = nullptr;
    for (int i = 0; i < n_in; i++) {
        if      (in_sizes[i] == 500000 * 32) data  = (const float*)d_in[i];
        else if (in_sizes[i] == 1024 * 32)   nodes = (const float*)d_in[i];
        else if (in_sizes[i] == 2000)        ridx  = (const int*)d_in[i];
    }
    som_train_kernel<<<1, 1024>>>(data, nodes, ridx, (float*)d_out);
}